// round 7
// baseline (speedup 1.0000x reference)
#include <cuda_runtime.h>
#include <math.h>
#include <stdint.h>

// Problem constants
#define NTOK 2048
#define DIM  1024
#define FF   4096
#define FSH  2048
#define NE   8
#define TOPK 2
#define NSLOT (NTOK*TOPK)

// Tiling: BM=128, BN=64, BK=16, double-buffered cp.async
#define BM 128
#define BN 64
#define BK 16
#define PA 20
#define PB 72

// ---- scratch ----
__device__ float g_act[(size_t)NSLOT * FF];
__device__ float g_eo[(size_t)NSLOT * DIM];
__device__ float g_hs[(size_t)NTOK * FSH];
__device__ float g_xr[(size_t)NTOK * DIM];
__device__ float w_gate[(size_t)NE * DIM * FF];
__device__ float w_up  [(size_t)NE * DIM * FF];
__device__ float w_down[(size_t)NE * FF * DIM];
__device__ float w_shg [(size_t)DIM * FSH];
__device__ float w_shu [(size_t)DIM * FSH];
__device__ float w_shd [(size_t)FSH * DIM];
__device__ float g_topw[NTOK * TOPK];
__device__ int   g_topi[NTOK * TOPK];
__device__ int   g_slot_tok[NSLOT];
__device__ float g_slot_w[NSLOT];
__device__ int   g_slot_dst[NSLOT];
__device__ int   g_cnt[NE];
__device__ int   g_off[NE + 1];

// ---------------------------------------------------------------------------
__device__ __forceinline__ uint32_t f2tf32(float x) {
    uint32_t r;
    asm("cvt.rna.tf32.f32 %0, %1;" : "=r"(r) : "f"(x));
    return r;
}

__device__ __forceinline__ void mma_tf32(float& c0, float& c1, float& c2, float& c3,
                                         uint32_t a0, uint32_t a1, uint32_t a2, uint32_t a3,
                                         uint32_t b0, uint32_t b1)
{
    asm volatile(
        "mma.sync.aligned.m16n8k8.row.col.f32.tf32.tf32.f32 "
        "{%0,%1,%2,%3},{%4,%5,%6,%7},{%8,%9},{%0,%1,%2,%3};"
        : "+f"(c0), "+f"(c1), "+f"(c2), "+f"(c3)
        : "r"(a0), "r"(a1), "r"(a2), "r"(a3), "r"(b0), "r"(b1));
}

__device__ __forceinline__ void cp16(uint32_t dst_smem, const float* src) {
    asm volatile("cp.async.cg.shared.global [%0], [%1], 16;"
                 :: "r"(dst_smem), "l"(src));
}
#define CP_COMMIT() asm volatile("cp.async.commit_group;")
#define CP_WAIT1()  asm volatile("cp.async.wait_group 1;" ::: "memory")

// Pre-round pass: elementwise cvt.rna.tf32, float4 vectorized.
__global__ void round_kernel(const float* __restrict__ src, float* __restrict__ dst)
{
    size_t i = (size_t)blockIdx.x * blockDim.x + threadIdx.x;
    float4 v = ((const float4*)src)[i];
    v.x = __uint_as_float(f2tf32(v.x));
    v.y = __uint_as_float(f2tf32(v.y));
    v.z = __uint_as_float(f2tf32(v.z));
    v.w = __uint_as_float(f2tf32(v.w));
    ((float4*)dst)[i] = v;
}

// ---------------------------------------------------------------------------
// Router + compaction (validated, unchanged)
// ---------------------------------------------------------------------------
__global__ void router_kernel(const float* __restrict__ x,
                              const float* __restrict__ gate_w)
{
    const int n = blockIdx.x;
    const int tid = threadIdx.x;
    __shared__ float sred[NE][128];

    float acc[NE];
#pragma unroll
    for (int e = 0; e < NE; e++) acc[e] = 0.f;

    const float* xr = x + (size_t)n * DIM;
    for (int d = tid; d < DIM; d += 128) {
        float xv = xr[d];
#pragma unroll
        for (int e = 0; e < NE; e++)
            acc[e] = fmaf(xv, gate_w[e * DIM + d], acc[e]);
    }
#pragma unroll
    for (int e = 0; e < NE; e++) sred[e][tid] = acc[e];
    __syncthreads();

    if (tid < NE) {
        float s = 0.f;
        for (int i = 0; i < 128; i++) s += sred[tid][i];
        sred[tid][0] = s;
    }
    __syncthreads();

    if (tid == 0) {
        float lg[NE];
#pragma unroll
        for (int e = 0; e < NE; e++) lg[e] = sred[e][0];
        float mx = lg[0];
#pragma unroll
        for (int e = 1; e < NE; e++) mx = fmaxf(mx, lg[e]);
        float se = 0.f, p[NE];
#pragma unroll
        for (int e = 0; e < NE; e++) { p[e] = expf(lg[e] - mx); se += p[e]; }
        float inv = 1.f / se;
#pragma unroll
        for (int e = 0; e < NE; e++) p[e] *= inv;

        int i1 = 0; float v1 = p[0];
#pragma unroll
        for (int e = 1; e < NE; e++) if (p[e] > v1) { v1 = p[e]; i1 = e; }
        int i2 = -1; float v2 = -1.f;
#pragma unroll
        for (int e = 0; e < NE; e++) if (e != i1 && p[e] > v2) { v2 = p[e]; i2 = e; }

        g_topi[n * 2 + 0] = i1;  g_topw[n * 2 + 0] = v1;
        g_topi[n * 2 + 1] = i2;  g_topw[n * 2 + 1] = v2;
        atomicAdd(&g_cnt[i1], 1);
        atomicAdd(&g_cnt[i2], 1);
    }
}

__global__ void zero_cnt_kernel()
{
    if (threadIdx.x < NE) g_cnt[threadIdx.x] = 0;
}

__global__ void scan_kernel()
{
    if (threadIdx.x == 0) {
        int r = 0;
        for (int e = 0; e < NE; e++) { g_off[e] = r; r += g_cnt[e]; g_cnt[e] = 0; }
        g_off[NE] = r;
    }
}

__global__ void fill_kernel()
{
    int n = blockIdx.x * blockDim.x + threadIdx.x;
    if (n >= NTOK) return;
#pragma unroll
    for (int k = 0; k < TOPK; k++) {
        int e = g_topi[n * 2 + k];
        int pos = atomicAdd(&g_cnt[e], 1);
        int slot = g_off[e] + pos;
        g_slot_tok[slot] = n;
        g_slot_w[slot]   = g_topw[n * 2 + k];
        g_slot_dst[slot] = n * 2 + k;
    }
}

// ---------------------------------------------------------------------------
// Routed gate+up GEMM + SwiGLU + weight (pre-rounded operands, no inner CVT)
// ---------------------------------------------------------------------------
__global__ __launch_bounds__(256)
void gemm_gateup_routed(const float* __restrict__ gate_k,
                        const float* __restrict__ up_k)
{
    const int e = blockIdx.z;
    const int cnt = g_cnt[e];
    const int rowbase = blockIdx.y * BM;
    if (rowbase >= cnt) return;
    const int off = g_off[e];
    const int n0 = blockIdx.x * BN;
    const float* __restrict__ Bg = gate_k + (size_t)e * DIM * FF;
    const float* __restrict__ Bu = up_k   + (size_t)e * DIM * FF;

    __shared__ float Am[2][BM * PA];
    __shared__ float Bgs[2][BK * PB];
    __shared__ float Bus[2][BK * PB];

    const int t = threadIdx.x;
    const int wid = t >> 5, lane = t & 31;
    const int q = lane >> 2, r = lane & 3;
    const int wm = (wid >> 1) * 32;
    const int wn = (wid & 1) * 32;

    const int a_row = t >> 1, a_seg = (t & 1) * 8;
    int m_g = rowbase + a_row;
    if (m_g >= cnt) m_g = cnt - 1;
    const float* a_src = g_xr + (size_t)g_slot_tok[off + m_g] * DIM + a_seg;

    const int b_row = t >> 4, b_col = (t & 15) * 4;
    const float* bg_src = Bg + (size_t)b_row * FF + n0 + b_col;
    const float* bu_src = Bu + (size_t)b_row * FF + n0 + b_col;

    const uint32_t sAm = (uint32_t)__cvta_generic_to_shared(&Am[0][0]);
    const uint32_t sBg = (uint32_t)__cvta_generic_to_shared(&Bgs[0][0]);
    const uint32_t sBu = (uint32_t)__cvta_generic_to_shared(&Bus[0][0]);
    const uint32_t aoff = (a_row * PA + a_seg) * 4;
    const uint32_t boff = (b_row * PB + b_col) * 4;
    const uint32_t szA = BM * PA * 4, szB = BK * PB * 4;

    float accg[2][4][4], accu[2][4][4];
#pragma unroll
    for (int i = 0; i < 2; i++)
#pragma unroll
        for (int j = 0; j < 4; j++)
#pragma unroll
            for (int c = 0; c < 4; c++) { accg[i][j][c] = 0.f; accu[i][j][c] = 0.f; }

    cp16(sAm + aoff,      a_src);
    cp16(sAm + aoff + 16, a_src + 4);
    cp16(sBg + boff, bg_src);
    cp16(sBu + boff, bu_src);
    CP_COMMIT();

#pragma unroll 1
    for (int k0 = 0; k0 < DIM; k0 += BK) {
        const int cur = (k0 >> 4) & 1;
        if (k0 + BK < DIM) {
            const uint32_t nb = (cur ^ 1);
            cp16(sAm + nb * szA + aoff,      a_src + k0 + BK);
            cp16(sAm + nb * szA + aoff + 16, a_src + k0 + BK + 4);
            cp16(sBg + nb * szB + boff, bg_src + (size_t)(k0 + BK) * FF);
            cp16(sBu + nb * szB + boff, bu_src + (size_t)(k0 + BK) * FF);
        }
        CP_COMMIT();
        CP_WAIT1();
        __syncthreads();

        const uint32_t* A_  = (const uint32_t*)Am[cur];
        const uint32_t* BG_ = (const uint32_t*)Bgs[cur];
        const uint32_t* BU_ = (const uint32_t*)Bus[cur];
#pragma unroll
        for (int ks = 0; ks < 2; ks++) {
            const int kb = ks * 8;
            uint32_t af[2][4];
#pragma unroll
            for (int mt = 0; mt < 2; mt++) {
                int mr = wm + mt * 16 + q;
                af[mt][0] = A_[mr * PA + kb + r];
                af[mt][1] = A_[(mr + 8) * PA + kb + r];
                af[mt][2] = A_[mr * PA + kb + 4 + r];
                af[mt][3] = A_[(mr + 8) * PA + kb + 4 + r];
            }
            uint32_t bgf[4][2], buf[4][2];
#pragma unroll
            for (int nt = 0; nt < 4; nt++) {
                int nc = wn + nt * 8 + q;
                bgf[nt][0] = BG_[(kb + r) * PB + nc];
                bgf[nt][1] = BG_[(kb + 4 + r) * PB + nc];
                buf[nt][0] = BU_[(kb + r) * PB + nc];
                buf[nt][1] = BU_[(kb + 4 + r) * PB + nc];
            }
#pragma unroll
            for (int mt = 0; mt < 2; mt++)
#pragma unroll
                for (int nt = 0; nt < 4; nt++) {
                    mma_tf32(accg[mt][nt][0], accg[mt][nt][1], accg[mt][nt][2], accg[mt][nt][3],
                             af[mt][0], af[mt][1], af[mt][2], af[mt][3], bgf[nt][0], bgf[nt][1]);
                    mma_tf32(accu[mt][nt][0], accu[mt][nt][1], accu[mt][nt][2], accu[mt][nt][3],
                             af[mt][0], af[mt][1], af[mt][2], af[mt][3], buf[nt][0], buf[nt][1]);
                }
        }
        __syncthreads();
    }

#pragma unroll
    for (int mt = 0; mt < 2; mt++) {
        int r0 = wm + mt * 16 + q;
#pragma unroll
        for (int half = 0; half < 2; half++) {
            int m = rowbase + r0 + half * 8;
            if (m < cnt) {
                int slot = off + m;
                float w = g_slot_w[slot];
                float* dst = g_act + (size_t)slot * FF + n0;
#pragma unroll
                for (int nt = 0; nt < 4; nt++) {
                    int cb = wn + nt * 8 + 2 * r;
                    float gv0 = accg[mt][nt][half * 2 + 0];
                    float gv1 = accg[mt][nt][half * 2 + 1];
                    float uv0 = accu[mt][nt][half * 2 + 0];
                    float uv1 = accu[mt][nt][half * 2 + 1];
                    // store pre-rounded so the down GEMM needs no CVT
                    dst[cb]     = __uint_as_float(f2tf32(w * (gv0 / (1.f + expf(-gv0))) * uv0));
                    dst[cb + 1] = __uint_as_float(f2tf32(w * (gv1 / (1.f + expf(-gv1))) * uv1));
                }
            }
        }
    }
}

// ---------------------------------------------------------------------------
// Routed down GEMM (pre-rounded operands)
// ---------------------------------------------------------------------------
__global__ __launch_bounds__(256)
void gemm_down_routed(const float* __restrict__ down_k)
{
    const int e = blockIdx.z;
    const int cnt = g_cnt[e];
    const int rowbase = blockIdx.y * BM;
    if (rowbase >= cnt) return;
    const int off = g_off[e];
    const int n0 = blockIdx.x * BN;
    const float* __restrict__ B = down_k + (size_t)e * FF * DIM;

    __shared__ float Am[2][BM * PA];
    __shared__ float Bs[2][BK * PB];

    const int t = threadIdx.x;
    const int wid = t >> 5, lane = t & 31;
    const int q = lane >> 2, r = lane & 3;
    const int wm = (wid >> 1) * 32;
    const int wn = (wid & 1) * 32;

    const int a_row = t >> 1, a_seg = (t & 1) * 8;
    int m_g = rowbase + a_row;
    if (m_g >= cnt) m_g = cnt - 1;
    const float* a_src = g_act + (size_t)(off + m_g) * FF + a_seg;

    const int b_row = t >> 4, b_col = (t & 15) * 4;
    const float* b_src = B + (size_t)b_row * DIM + n0 + b_col;

    const uint32_t sAm = (uint32_t)__cvta_generic_to_shared(&Am[0][0]);
    const uint32_t sBs = (uint32_t)__cvta_generic_to_shared(&Bs[0][0]);
    const uint32_t aoff = (a_row * PA + a_seg) * 4;
    const uint32_t boff = (b_row * PB + b_col) * 4;
    const uint32_t szA = BM * PA * 4, szB = BK * PB * 4;

    float acc[2][4][4];
#pragma unroll
    for (int i = 0; i < 2; i++)
#pragma unroll
        for (int j = 0; j < 4; j++)
#pragma unroll
            for (int c = 0; c < 4; c++) acc[i][j][c] = 0.f;

    cp16(sAm + aoff,      a_src);
    cp16(sAm + aoff + 16, a_src + 4);
    cp16(sBs + boff, b_src);
    CP_COMMIT();

#pragma unroll 1
    for (int k0 = 0; k0 < FF; k0 += BK) {
        const int cur = (k0 >> 4) & 1;
        if (k0 + BK < FF) {
            const uint32_t nb = (cur ^ 1);
            cp16(sAm + nb * szA + aoff,      a_src + k0 + BK);
            cp16(sAm + nb * szA + aoff + 16, a_src + k0 + BK + 4);
            cp16(sBs + nb * szB + boff, b_src + (size_t)(k0 + BK) * DIM);
        }
        CP_COMMIT();
        CP_WAIT1();
        __syncthreads();

        const uint32_t* A_ = (const uint32_t*)Am[cur];
        const uint32_t* B_ = (const uint32_t*)Bs[cur];
#pragma unroll
        for (int ks = 0; ks < 2; ks++) {
            const int kb = ks * 8;
            uint32_t af[2][4];
#pragma unroll
            for (int mt = 0; mt < 2; mt++) {
                int mr = wm + mt * 16 + q;
                af[mt][0] = A_[mr * PA + kb + r];
                af[mt][1] = A_[(mr + 8) * PA + kb + r];
                af[mt][2] = A_[mr * PA + kb + 4 + r];
                af[mt][3] = A_[(mr + 8) * PA + kb + 4 + r];
            }
            uint32_t bf[4][2];
#pragma unroll
            for (int nt = 0; nt < 4; nt++) {
                int nc = wn + nt * 8 + q;
                bf[nt][0] = B_[(kb + r) * PB + nc];
                bf[nt][1] = B_[(kb + 4 + r) * PB + nc];
            }
#pragma unroll
            for (int mt = 0; mt < 2; mt++)
#pragma unroll
                for (int nt = 0; nt < 4; nt++)
                    mma_tf32(acc[mt][nt][0], acc[mt][nt][1], acc[mt][nt][2], acc[mt][nt][3],
                             af[mt][0], af[mt][1], af[mt][2], af[mt][3], bf[nt][0], bf[nt][1]);
        }
        __syncthreads();
    }

#pragma unroll
    for (int mt = 0; mt < 2; mt++) {
        int r0 = wm + mt * 16 + q;
#pragma unroll
        for (int half = 0; half < 2; half++) {
            int m = rowbase + r0 + half * 8;
            if (m < cnt) {
                int dst_row = g_slot_dst[off + m];
                float* dst = g_eo + (size_t)dst_row * DIM + n0;
#pragma unroll
                for (int nt = 0; nt < 4; nt++) {
                    int cb = wn + nt * 8 + 2 * r;
                    dst[cb]     = acc[mt][nt][half * 2 + 0];
                    dst[cb + 1] = acc[mt][nt][half * 2 + 1];
                }
            }
        }
    }
}

// ---------------------------------------------------------------------------
// Shared expert gate+up + SwiGLU (pre-rounded operands)
// ---------------------------------------------------------------------------
__global__ __launch_bounds__(256)
void gemm_gateup_shared(const float* __restrict__ sh_gate,
                        const float* __restrict__ sh_up)
{
    const int rowbase = blockIdx.y * BM;
    const int n0 = blockIdx.x * BN;

    __shared__ float Am[2][BM * PA];
    __shared__ float Bgs[2][BK * PB];
    __shared__ float Bus[2][BK * PB];

    const int t = threadIdx.x;
    const int wid = t >> 5, lane = t & 31;
    const int q = lane >> 2, r = lane & 3;
    const int wm = (wid >> 1) * 32;
    const int wn = (wid & 1) * 32;

    const int a_row = t >> 1, a_seg = (t & 1) * 8;
    const float* a_src = g_xr + (size_t)(rowbase + a_row) * DIM + a_seg;

    const int b_row = t >> 4, b_col = (t & 15) * 4;
    const float* bg_src = sh_gate + (size_t)b_row * FSH + n0 + b_col;
    const float* bu_src = sh_up   + (size_t)b_row * FSH + n0 + b_col;

    const uint32_t sAm = (uint32_t)__cvta_generic_to_shared(&Am[0][0]);
    const uint32_t sBg = (uint32_t)__cvta_generic_to_shared(&Bgs[0][0]);
    const uint32_t sBu = (uint32_t)__cvta_generic_to_shared(&Bus[0][0]);
    const uint32_t aoff = (a_row * PA + a_seg) * 4;
    const uint32_t boff = (b_row * PB + b_col) * 4;
    const uint32_t szA = BM * PA * 4, szB = BK * PB * 4;

    float accg[2][4][4], accu[2][4][4];
#pragma unroll
    for (int i = 0; i < 2; i++)
#pragma unroll
        for (int j = 0; j < 4; j++)
#pragma unroll
            for (int c = 0; c < 4; c++) { accg[i][j][c] = 0.f; accu[i][j][c] = 0.f; }

    cp16(sAm + aoff,      a_src);
    cp16(sAm + aoff + 16, a_src + 4);
    cp16(sBg + boff, bg_src);
    cp16(sBu + boff, bu_src);
    CP_COMMIT();

#pragma unroll 1
    for (int k0 = 0; k0 < DIM; k0 += BK) {
        const int cur = (k0 >> 4) & 1;
        if (k0 + BK < DIM) {
            const uint32_t nb = (cur ^ 1);
            cp16(sAm + nb * szA + aoff,      a_src + k0 + BK);
            cp16(sAm + nb * szA + aoff + 16, a_src + k0 + BK + 4);
            cp16(sBg + nb * szB + boff, bg_src + (size_t)(k0 + BK) * FSH);
            cp16(sBu + nb * szB + boff, bu_src + (size_t)(k0 + BK) * FSH);
        }
        CP_COMMIT();
        CP_WAIT1();
        __syncthreads();

        const uint32_t* A_  = (const uint32_t*)Am[cur];
        const uint32_t* BG_ = (const uint32_t*)Bgs[cur];
        const uint32_t* BU_ = (const uint32_t*)Bus[cur];
#pragma unroll
        for (int ks = 0; ks < 2; ks++) {
            const int kb = ks * 8;
            uint32_t af[2][4];
#pragma unroll
            for (int mt = 0; mt < 2; mt++) {
                int mr = wm + mt * 16 + q;
                af[mt][0] = A_[mr * PA + kb + r];
                af[mt][1] = A_[(mr + 8) * PA + kb + r];
                af[mt][2] = A_[mr * PA + kb + 4 + r];
                af[mt][3] = A_[(mr + 8) * PA + kb + 4 + r];
            }
            uint32_t bgf[4][2], buf[4][2];
#pragma unroll
            for (int nt = 0; nt < 4; nt++) {
                int nc = wn + nt * 8 + q;
                bgf[nt][0] = BG_[(kb + r) * PB + nc];
                bgf[nt][1] = BG_[(kb + 4 + r) * PB + nc];
                buf[nt][0] = BU_[(kb + r) * PB + nc];
                buf[nt][1] = BU_[(kb + 4 + r) * PB + nc];
            }
#pragma unroll
            for (int mt = 0; mt < 2; mt++)
#pragma unroll
                for (int nt = 0; nt < 4; nt++) {
                    mma_tf32(accg[mt][nt][0], accg[mt][nt][1], accg[mt][nt][2], accg[mt][nt][3],
                             af[mt][0], af[mt][1], af[mt][2], af[mt][3], bgf[nt][0], bgf[nt][1]);
                    mma_tf32(accu[mt][nt][0], accu[mt][nt][1], accu[mt][nt][2], accu[mt][nt][3],
                             af[mt][0], af[mt][1], af[mt][2], af[mt][3], buf[nt][0], buf[nt][1]);
                }
        }
        __syncthreads();
    }

#pragma unroll
    for (int mt = 0; mt < 2; mt++) {
        int r0 = wm + mt * 16 + q;
#pragma unroll
        for (int half = 0; half < 2; half++) {
            int m = rowbase + r0 + half * 8;
            float* dst = g_hs + (size_t)m * FSH + n0;
#pragma unroll
            for (int nt = 0; nt < 4; nt++) {
                int cb = wn + nt * 8 + 2 * r;
                float gv0 = accg[mt][nt][half * 2 + 0];
                float gv1 = accg[mt][nt][half * 2 + 1];
                float uv0 = accu[mt][nt][half * 2 + 0];
                float uv1 = accu[mt][nt][half * 2 + 1];
                dst[cb]     = __uint_as_float(f2tf32((gv0 / (1.f + expf(-gv0))) * uv0));
                dst[cb + 1] = __uint_as_float(f2tf32((gv1 / (1.f + expf(-gv1))) * uv1));
            }
        }
    }
}

// ---------------------------------------------------------------------------
// Shared down GEMM + final combine (pre-rounded operands)
// ---------------------------------------------------------------------------
__global__ __launch_bounds__(256)
void gemm_down_shared(const float* __restrict__ sh_down,
                      float* __restrict__ out)
{
    const int rowbase = blockIdx.y * BM;
    const int n0 = blockIdx.x * BN;

    __shared__ float Am[2][BM * PA];
    __shared__ float Bs[2][BK * PB];

    const int t = threadIdx.x;
    const int wid = t >> 5, lane = t & 31;
    const int q = lane >> 2, r = lane & 3;
    const int wm = (wid >> 1) * 32;
    const int wn = (wid & 1) * 32;

    const int a_row = t >> 1, a_seg = (t & 1) * 8;
    const float* a_src = g_hs + (size_t)(rowbase + a_row) * FSH + a_seg;

    const int b_row = t >> 4, b_col = (t & 15) * 4;
    const float* b_src = sh_down + (size_t)b_row * DIM + n0 + b_col;

    const uint32_t sAm = (uint32_t)__cvta_generic_to_shared(&Am[0][0]);
    const uint32_t sBs = (uint32_t)__cvta_generic_to_shared(&Bs[0][0]);
    const uint32_t aoff = (a_row * PA + a_seg) * 4;
    const uint32_t boff = (b_row * PB + b_col) * 4;
    const uint32_t szA = BM * PA * 4, szB = BK * PB * 4;

    float acc[2][4][4];
#pragma unroll
    for (int i = 0; i < 2; i++)
#pragma unroll
        for (int j = 0; j < 4; j++)
#pragma unroll
            for (int c = 0; c < 4; c++) acc[i][j][c] = 0.f;

    cp16(sAm + aoff,      a_src);
    cp16(sAm + aoff + 16, a_src + 4);
    cp16(sBs + boff, b_src);
    CP_COMMIT();

#pragma unroll 1
    for (int k0 = 0; k0 < FSH; k0 += BK) {
        const int cur = (k0 >> 4) & 1;
        if (k0 + BK < FSH) {
            const uint32_t nb = (cur ^ 1);
            cp16(sAm + nb * szA + aoff,      a_src + k0 + BK);
            cp16(sAm + nb * szA + aoff + 16, a_src + k0 + BK + 4);
            cp16(sBs + nb * szB + boff, b_src + (size_t)(k0 + BK) * DIM);
        }
        CP_COMMIT();
        CP_WAIT1();
        __syncthreads();

        const uint32_t* A_ = (const uint32_t*)Am[cur];
        const uint32_t* B_ = (const uint32_t*)Bs[cur];
#pragma unroll
        for (int ks = 0; ks < 2; ks++) {
            const int kb = ks * 8;
            uint32_t af[2][4];
#pragma unroll
            for (int mt = 0; mt < 2; mt++) {
                int mr = wm + mt * 16 + q;
                af[mt][0] = A_[mr * PA + kb + r];
                af[mt][1] = A_[(mr + 8) * PA + kb + r];
                af[mt][2] = A_[mr * PA + kb + 4 + r];
                af[mt][3] = A_[(mr + 8) * PA + kb + 4 + r];
            }
            uint32_t bf[4][2];
#pragma unroll
            for (int nt = 0; nt < 4; nt++) {
                int nc = wn + nt * 8 + q;
                bf[nt][0] = B_[(kb + r) * PB + nc];
                bf[nt][1] = B_[(kb + 4 + r) * PB + nc];
            }
#pragma unroll
            for (int mt = 0; mt < 2; mt++)
#pragma unroll
                for (int nt = 0; nt < 4; nt++)
                    mma_tf32(acc[mt][nt][0], acc[mt][nt][1], acc[mt][nt][2], acc[mt][nt][3],
                             af[mt][0], af[mt][1], af[mt][2], af[mt][3], bf[nt][0], bf[nt][1]);
        }
        __syncthreads();
    }

#pragma unroll
    for (int mt = 0; mt < 2; mt++) {
        int r0 = wm + mt * 16 + q;
#pragma unroll
        for (int half = 0; half < 2; half++) {
            int m = rowbase + r0 + half * 8;
            const float* eo0 = g_eo + (size_t)(m * 2)     * DIM + n0;
            const float* eo1 = g_eo + (size_t)(m * 2 + 1) * DIM + n0;
            float* dst = out + (size_t)m * DIM + n0;
#pragma unroll
            for (int nt = 0; nt < 4; nt++) {
                int cb = wn + nt * 8 + 2 * r;
                dst[cb]     = acc[mt][nt][half * 2 + 0] + eo0[cb]     + eo1[cb];
                dst[cb + 1] = acc[mt][nt][half * 2 + 1] + eo0[cb + 1] + eo1[cb + 1];
            }
        }
    }
}

// ---------------------------------------------------------------------------
extern "C" void kernel_launch(void* const* d_in, const int* in_sizes, int n_in,
                              void* d_out, int out_size)
{
    const float* x       = (const float*)d_in[0];
    const float* gate_w  = (const float*)d_in[1];
    const float* gate_k  = (const float*)d_in[2];
    const float* up_k    = (const float*)d_in[3];
    const float* down_k  = (const float*)d_in[4];
    const float* sh_gate = (const float*)d_in[5];
    const float* sh_up   = (const float*)d_in[6];
    const float* sh_down = (const float*)d_in[7];
    float* out = (float*)d_out;

    zero_cnt_kernel<<<1, 32>>>();
    router_kernel<<<NTOK, 128>>>(x, gate_w);
    scan_kernel<<<1, 32>>>();
    fill_kernel<<<NTOK / 256, 256>>>();

    // pre-round all operands to tf32 (RNA) once
    float* dst_x;  cudaGetSymbolAddress((void**)&dst_x,  g_xr);
    float* dst_g;  cudaGetSymbolAddress((void**)&dst_g,  w_gate);
    float* dst_u;  cudaGetSymbolAddress((void**)&dst_u,  w_up);
    float* dst_d;  cudaGetSymbolAddress((void**)&dst_d,  w_down);
    float* dst_sg; cudaGetSymbolAddress((void**)&dst_sg, w_shg);
    float* dst_su; cudaGetSymbolAddress((void**)&dst_su, w_shu);
    float* dst_sd; cudaGetSymbolAddress((void**)&dst_sd, w_shd);

    round_kernel<<<NTOK * DIM / 4 / 256, 256>>>(x, dst_x);
    round_kernel<<<(size_t)NE * DIM * FF / 4 / 256, 256>>>(gate_k, dst_g);
    round_kernel<<<(size_t)NE * DIM * FF / 4 / 256, 256>>>(up_k, dst_u);
    round_kernel<<<(size_t)NE * FF * DIM / 4 / 256, 256>>>(down_k, dst_d);
    round_kernel<<<(size_t)DIM * FSH / 4 / 256, 256>>>(sh_gate, dst_sg);
    round_kernel<<<(size_t)DIM * FSH / 4 / 256, 256>>>(sh_up, dst_su);
    round_kernel<<<(size_t)FSH * DIM / 4 / 256, 256>>>(sh_down, dst_sd);

    gemm_gateup_routed<<<dim3(FF / BN, NTOK / BM, NE), 256>>>(dst_g, dst_u);
    gemm_down_routed<<<dim3(DIM / BN, NTOK / BM, NE), 256>>>(dst_d);
    gemm_gateup_shared<<<dim3(FSH / BN, NTOK / BM), 256>>>(dst_sg, dst_su);
    gemm_down_shared<<<dim3(DIM / BN, NTOK / BM), 256>>>(dst_sd, out);
}

// round 8
// speedup vs baseline: 1.0162x; 1.0162x over previous
#include <cuda_runtime.h>
#include <math.h>
#include <stdint.h>

// Problem constants
#define NTOK 2048
#define DIM  1024
#define FF   4096
#define FSH  2048
#define NE   8
#define TOPK 2
#define NSLOT (NTOK*TOPK)

// Tiling: BM=128, BN=64, BK=32, double-buffered cp.async, dynamic smem
#define BM 128
#define BN 64
#define BK 32
#define PA 36      // A smem pitch [m][k]: banks (36q + r) % 32 = 4q+r, conflict-free
#define PB 72      // B smem pitch [k][n]: banks (72r + q) % 32 = 8r+q, conflict-free

#define SZA_F (BM * PA)          // 4608 floats per A buffer
#define SZB_F (BK * PB)          // 2304 floats per B buffer
#define SMEM_DUAL_B ((2*SZA_F + 4*SZB_F) * 4)   // 73728 B
#define SMEM_SING_B ((2*SZA_F + 2*SZB_F) * 4)   // 55296 B

// ---- scratch ----
__device__ float g_act[(size_t)NSLOT * FF];
__device__ float g_eo[(size_t)NSLOT * DIM];
__device__ float g_hs[(size_t)NTOK * FSH];
__device__ float g_topw[NTOK * TOPK];
__device__ int   g_topi[NTOK * TOPK];
__device__ int   g_slot_tok[NSLOT];
__device__ float g_slot_w[NSLOT];
__device__ int   g_slot_dst[NSLOT];
__device__ int   g_cnt[NE];
__device__ int   g_off[NE + 1];

// ---------------------------------------------------------------------------
__device__ __forceinline__ uint32_t f2tf32(float x) {
    uint32_t r;
    asm("cvt.rna.tf32.f32 %0, %1;" : "=r"(r) : "f"(x));
    return r;
}

__device__ __forceinline__ void mma_tf32(float& c0, float& c1, float& c2, float& c3,
                                         uint32_t a0, uint32_t a1, uint32_t a2, uint32_t a3,
                                         uint32_t b0, uint32_t b1)
{
    asm volatile(
        "mma.sync.aligned.m16n8k8.row.col.f32.tf32.tf32.f32 "
        "{%0,%1,%2,%3},{%4,%5,%6,%7},{%8,%9},{%0,%1,%2,%3};"
        : "+f"(c0), "+f"(c1), "+f"(c2), "+f"(c3)
        : "r"(a0), "r"(a1), "r"(a2), "r"(a3), "r"(b0), "r"(b1));
}

__device__ __forceinline__ void cp16(uint32_t dst_smem, const float* src) {
    asm volatile("cp.async.cg.shared.global [%0], [%1], 16;"
                 :: "r"(dst_smem), "l"(src));
}
#define CP_COMMIT() asm volatile("cp.async.commit_group;")
#define CP_WAIT1()  asm volatile("cp.async.wait_group 1;" ::: "memory")

// ---------------------------------------------------------------------------
// Router + compaction (validated, unchanged)
// ---------------------------------------------------------------------------
__global__ void router_kernel(const float* __restrict__ x,
                              const float* __restrict__ gate_w)
{
    const int n = blockIdx.x;
    const int tid = threadIdx.x;
    __shared__ float sred[NE][128];

    float acc[NE];
#pragma unroll
    for (int e = 0; e < NE; e++) acc[e] = 0.f;

    const float* xr = x + (size_t)n * DIM;
    for (int d = tid; d < DIM; d += 128) {
        float xv = xr[d];
#pragma unroll
        for (int e = 0; e < NE; e++)
            acc[e] = fmaf(xv, gate_w[e * DIM + d], acc[e]);
    }
#pragma unroll
    for (int e = 0; e < NE; e++) sred[e][tid] = acc[e];
    __syncthreads();

    if (tid < NE) {
        float s = 0.f;
        for (int i = 0; i < 128; i++) s += sred[tid][i];
        sred[tid][0] = s;
    }
    __syncthreads();

    if (tid == 0) {
        float lg[NE];
#pragma unroll
        for (int e = 0; e < NE; e++) lg[e] = sred[e][0];
        float mx = lg[0];
#pragma unroll
        for (int e = 1; e < NE; e++) mx = fmaxf(mx, lg[e]);
        float se = 0.f, p[NE];
#pragma unroll
        for (int e = 0; e < NE; e++) { p[e] = expf(lg[e] - mx); se += p[e]; }
        float inv = 1.f / se;
#pragma unroll
        for (int e = 0; e < NE; e++) p[e] *= inv;

        int i1 = 0; float v1 = p[0];
#pragma unroll
        for (int e = 1; e < NE; e++) if (p[e] > v1) { v1 = p[e]; i1 = e; }
        int i2 = -1; float v2 = -1.f;
#pragma unroll
        for (int e = 0; e < NE; e++) if (e != i1 && p[e] > v2) { v2 = p[e]; i2 = e; }

        g_topi[n * 2 + 0] = i1;  g_topw[n * 2 + 0] = v1;
        g_topi[n * 2 + 1] = i2;  g_topw[n * 2 + 1] = v2;
        atomicAdd(&g_cnt[i1], 1);
        atomicAdd(&g_cnt[i2], 1);
    }
}

__global__ void zero_cnt_kernel()
{
    if (threadIdx.x < NE) g_cnt[threadIdx.x] = 0;
}

__global__ void scan_kernel()
{
    if (threadIdx.x == 0) {
        int r = 0;
        for (int e = 0; e < NE; e++) { g_off[e] = r; r += g_cnt[e]; g_cnt[e] = 0; }
        g_off[NE] = r;
    }
}

__global__ void fill_kernel()
{
    int n = blockIdx.x * blockDim.x + threadIdx.x;
    if (n >= NTOK) return;
#pragma unroll
    for (int k = 0; k < TOPK; k++) {
        int e = g_topi[n * 2 + k];
        int pos = atomicAdd(&g_cnt[e], 1);
        int slot = g_off[e] + pos;
        g_slot_tok[slot] = n;
        g_slot_w[slot]   = g_topw[n * 2 + k];
        g_slot_dst[slot] = n * 2 + k;
    }
}

// ---------------------------------------------------------------------------
// Routed gate+up GEMM + SwiGLU + weight  (BK=32, M-tile-fastest grid)
// grid: (NTOK/BM, FF/BN, NE)
// ---------------------------------------------------------------------------
__global__ __launch_bounds__(256)
void gemm_gateup_routed(const float* __restrict__ x,
                        const float* __restrict__ gate_k,
                        const float* __restrict__ up_k)
{
    const int e = blockIdx.z;
    const int cnt = g_cnt[e];
    const int rowbase = blockIdx.x * BM;
    if (rowbase >= cnt) return;
    const int off = g_off[e];
    const int n0 = blockIdx.y * BN;
    const float* __restrict__ Bg = gate_k + (size_t)e * DIM * FF;
    const float* __restrict__ Bu = up_k   + (size_t)e * DIM * FF;

    extern __shared__ float smf[];
    float* Am  = smf;                      // 2 x SZA_F
    float* Bgs = smf + 2 * SZA_F;          // 2 x SZB_F
    float* Bus = smf + 2 * SZA_F + 2 * SZB_F;

    const int t = threadIdx.x;
    const int wid = t >> 5, lane = t & 31;
    const int q = lane >> 2, r = lane & 3;
    const int wm = (wid >> 1) * 32;
    const int wn = (wid & 1) * 32;

    // loaders: A 128x32 (16 floats/thread = 4 cp16), B 32x64 (8 floats = 2 cp16)
    const int a_row = t >> 1, a_seg = (t & 1) * 16;
    int m_g = rowbase + a_row;
    if (m_g >= cnt) m_g = cnt - 1;
    const float* a_src = x + (size_t)g_slot_tok[off + m_g] * DIM + a_seg;

    const int b_row = t >> 3, b_col = (t & 7) * 8;
    const float* bg_src = Bg + (size_t)b_row * FF + n0 + b_col;
    const float* bu_src = Bu + (size_t)b_row * FF + n0 + b_col;

    const uint32_t sAm = (uint32_t)__cvta_generic_to_shared(Am);
    const uint32_t sBg = (uint32_t)__cvta_generic_to_shared(Bgs);
    const uint32_t sBu = (uint32_t)__cvta_generic_to_shared(Bus);
    const uint32_t aoff = (a_row * PA + a_seg) * 4;
    const uint32_t boff = (b_row * PB + b_col) * 4;
    const uint32_t szA = SZA_F * 4, szB = SZB_F * 4;

    float accg[2][4][4], accu[2][4][4];
#pragma unroll
    for (int i = 0; i < 2; i++)
#pragma unroll
        for (int j = 0; j < 4; j++)
#pragma unroll
            for (int c = 0; c < 4; c++) { accg[i][j][c] = 0.f; accu[i][j][c] = 0.f; }

    // prologue: chunk 0 -> buffer 0
#pragma unroll
    for (int l = 0; l < 4; l++) cp16(sAm + aoff + l * 16, a_src + l * 4);
    cp16(sBg + boff, bg_src);      cp16(sBg + boff + 16, bg_src + 4);
    cp16(sBu + boff, bu_src);      cp16(sBu + boff + 16, bu_src + 4);
    CP_COMMIT();

#pragma unroll 1
    for (int k0 = 0; k0 < DIM; k0 += BK) {
        const int cur = (k0 >> 5) & 1;
        if (k0 + BK < DIM) {
            const uint32_t nb = cur ^ 1;
#pragma unroll
            for (int l = 0; l < 4; l++)
                cp16(sAm + nb * szA + aoff + l * 16, a_src + k0 + BK + l * 4);
            const float* bgn = bg_src + (size_t)(k0 + BK) * FF;
            const float* bun = bu_src + (size_t)(k0 + BK) * FF;
            cp16(sBg + nb * szB + boff, bgn);      cp16(sBg + nb * szB + boff + 16, bgn + 4);
            cp16(sBu + nb * szB + boff, bun);      cp16(sBu + nb * szB + boff + 16, bun + 4);
        }
        CP_COMMIT();
        CP_WAIT1();
        __syncthreads();

        const float* A_  = Am  + cur * SZA_F;
        const float* BG_ = Bgs + cur * SZB_F;
        const float* BU_ = Bus + cur * SZB_F;
#pragma unroll
        for (int ks = 0; ks < 4; ks++) {
            const int kb = ks * 8;
            uint32_t af[2][4];
#pragma unroll
            for (int mt = 0; mt < 2; mt++) {
                int mr = wm + mt * 16 + q;
                af[mt][0] = f2tf32(A_[mr * PA + kb + r]);
                af[mt][1] = f2tf32(A_[(mr + 8) * PA + kb + r]);
                af[mt][2] = f2tf32(A_[mr * PA + kb + 4 + r]);
                af[mt][3] = f2tf32(A_[(mr + 8) * PA + kb + 4 + r]);
            }
            uint32_t bgf[4][2], buf[4][2];
#pragma unroll
            for (int nt = 0; nt < 4; nt++) {
                int nc = wn + nt * 8 + q;
                bgf[nt][0] = f2tf32(BG_[(kb + r) * PB + nc]);
                bgf[nt][1] = f2tf32(BG_[(kb + 4 + r) * PB + nc]);
                buf[nt][0] = f2tf32(BU_[(kb + r) * PB + nc]);
                buf[nt][1] = f2tf32(BU_[(kb + 4 + r) * PB + nc]);
            }
#pragma unroll
            for (int mt = 0; mt < 2; mt++)
#pragma unroll
                for (int nt = 0; nt < 4; nt++) {
                    mma_tf32(accg[mt][nt][0], accg[mt][nt][1], accg[mt][nt][2], accg[mt][nt][3],
                             af[mt][0], af[mt][1], af[mt][2], af[mt][3], bgf[nt][0], bgf[nt][1]);
                    mma_tf32(accu[mt][nt][0], accu[mt][nt][1], accu[mt][nt][2], accu[mt][nt][3],
                             af[mt][0], af[mt][1], af[mt][2], af[mt][3], buf[nt][0], buf[nt][1]);
                }
        }
        __syncthreads();
    }

#pragma unroll
    for (int mt = 0; mt < 2; mt++) {
        int r0 = wm + mt * 16 + q;
#pragma unroll
        for (int half = 0; half < 2; half++) {
            int m = rowbase + r0 + half * 8;
            if (m < cnt) {
                int slot = off + m;
                float w = g_slot_w[slot];
                float* dst = g_act + (size_t)slot * FF + n0;
#pragma unroll
                for (int nt = 0; nt < 4; nt++) {
                    int cb = wn + nt * 8 + 2 * r;
                    float gv0 = accg[mt][nt][half * 2 + 0];
                    float gv1 = accg[mt][nt][half * 2 + 1];
                    float uv0 = accu[mt][nt][half * 2 + 0];
                    float uv1 = accu[mt][nt][half * 2 + 1];
                    dst[cb]     = w * (gv0 / (1.f + expf(-gv0))) * uv0;
                    dst[cb + 1] = w * (gv1 / (1.f + expf(-gv1))) * uv1;
                }
            }
        }
    }
}

// ---------------------------------------------------------------------------
// Routed down GEMM (BK=32, M-tile-fastest grid)  grid: (NTOK/BM, DIM/BN, NE)
// ---------------------------------------------------------------------------
__global__ __launch_bounds__(256)
void gemm_down_routed(const float* __restrict__ down_k)
{
    const int e = blockIdx.z;
    const int cnt = g_cnt[e];
    const int rowbase = blockIdx.x * BM;
    if (rowbase >= cnt) return;
    const int off = g_off[e];
    const int n0 = blockIdx.y * BN;
    const float* __restrict__ B = down_k + (size_t)e * FF * DIM;

    extern __shared__ float smf[];
    float* Am = smf;
    float* Bs = smf + 2 * SZA_F;

    const int t = threadIdx.x;
    const int wid = t >> 5, lane = t & 31;
    const int q = lane >> 2, r = lane & 3;
    const int wm = (wid >> 1) * 32;
    const int wn = (wid & 1) * 32;

    const int a_row = t >> 1, a_seg = (t & 1) * 16;
    int m_g = rowbase + a_row;
    if (m_g >= cnt) m_g = cnt - 1;
    const float* a_src = g_act + (size_t)(off + m_g) * FF + a_seg;

    const int b_row = t >> 3, b_col = (t & 7) * 8;
    const float* b_src = B + (size_t)b_row * DIM + n0 + b_col;

    const uint32_t sAm = (uint32_t)__cvta_generic_to_shared(Am);
    const uint32_t sBs = (uint32_t)__cvta_generic_to_shared(Bs);
    const uint32_t aoff = (a_row * PA + a_seg) * 4;
    const uint32_t boff = (b_row * PB + b_col) * 4;
    const uint32_t szA = SZA_F * 4, szB = SZB_F * 4;

    float acc[2][4][4];
#pragma unroll
    for (int i = 0; i < 2; i++)
#pragma unroll
        for (int j = 0; j < 4; j++)
#pragma unroll
            for (int c = 0; c < 4; c++) acc[i][j][c] = 0.f;

#pragma unroll
    for (int l = 0; l < 4; l++) cp16(sAm + aoff + l * 16, a_src + l * 4);
    cp16(sBs + boff, b_src);  cp16(sBs + boff + 16, b_src + 4);
    CP_COMMIT();

#pragma unroll 1
    for (int k0 = 0; k0 < FF; k0 += BK) {
        const int cur = (k0 >> 5) & 1;
        if (k0 + BK < FF) {
            const uint32_t nb = cur ^ 1;
#pragma unroll
            for (int l = 0; l < 4; l++)
                cp16(sAm + nb * szA + aoff + l * 16, a_src + k0 + BK + l * 4);
            const float* bn = b_src + (size_t)(k0 + BK) * DIM;
            cp16(sBs + nb * szB + boff, bn);  cp16(sBs + nb * szB + boff + 16, bn + 4);
        }
        CP_COMMIT();
        CP_WAIT1();
        __syncthreads();

        const float* A_ = Am + cur * SZA_F;
        const float* B_ = Bs + cur * SZB_F;
#pragma unroll
        for (int ks = 0; ks < 4; ks++) {
            const int kb = ks * 8;
            uint32_t af[2][4];
#pragma unroll
            for (int mt = 0; mt < 2; mt++) {
                int mr = wm + mt * 16 + q;
                af[mt][0] = f2tf32(A_[mr * PA + kb + r]);
                af[mt][1] = f2tf32(A_[(mr + 8) * PA + kb + r]);
                af[mt][2] = f2tf32(A_[mr * PA + kb + 4 + r]);
                af[mt][3] = f2tf32(A_[(mr + 8) * PA + kb + 4 + r]);
            }
            uint32_t bf[4][2];
#pragma unroll
            for (int nt = 0; nt < 4; nt++) {
                int nc = wn + nt * 8 + q;
                bf[nt][0] = f2tf32(B_[(kb + r) * PB + nc]);
                bf[nt][1] = f2tf32(B_[(kb + 4 + r) * PB + nc]);
            }
#pragma unroll
            for (int mt = 0; mt < 2; mt++)
#pragma unroll
                for (int nt = 0; nt < 4; nt++)
                    mma_tf32(acc[mt][nt][0], acc[mt][nt][1], acc[mt][nt][2], acc[mt][nt][3],
                             af[mt][0], af[mt][1], af[mt][2], af[mt][3], bf[nt][0], bf[nt][1]);
        }
        __syncthreads();
    }

#pragma unroll
    for (int mt = 0; mt < 2; mt++) {
        int r0 = wm + mt * 16 + q;
#pragma unroll
        for (int half = 0; half < 2; half++) {
            int m = rowbase + r0 + half * 8;
            if (m < cnt) {
                int dst_row = g_slot_dst[off + m];
                float* dst = g_eo + (size_t)dst_row * DIM + n0;
#pragma unroll
                for (int nt = 0; nt < 4; nt++) {
                    int cb = wn + nt * 8 + 2 * r;
                    dst[cb]     = acc[mt][nt][half * 2 + 0];
                    dst[cb + 1] = acc[mt][nt][half * 2 + 1];
                }
            }
        }
    }
}

// ---------------------------------------------------------------------------
// Shared expert gate+up + SwiGLU (BK=32)  grid: (NTOK/BM, FSH/BN)
// ---------------------------------------------------------------------------
__global__ __launch_bounds__(256)
void gemm_gateup_shared(const float* __restrict__ x,
                        const float* __restrict__ sh_gate,
                        const float* __restrict__ sh_up)
{
    const int rowbase = blockIdx.x * BM;
    const int n0 = blockIdx.y * BN;

    extern __shared__ float smf[];
    float* Am  = smf;
    float* Bgs = smf + 2 * SZA_F;
    float* Bus = smf + 2 * SZA_F + 2 * SZB_F;

    const int t = threadIdx.x;
    const int wid = t >> 5, lane = t & 31;
    const int q = lane >> 2, r = lane & 3;
    const int wm = (wid >> 1) * 32;
    const int wn = (wid & 1) * 32;

    const int a_row = t >> 1, a_seg = (t & 1) * 16;
    const float* a_src = x + (size_t)(rowbase + a_row) * DIM + a_seg;

    const int b_row = t >> 3, b_col = (t & 7) * 8;
    const float* bg_src = sh_gate + (size_t)b_row * FSH + n0 + b_col;
    const float* bu_src = sh_up   + (size_t)b_row * FSH + n0 + b_col;

    const uint32_t sAm = (uint32_t)__cvta_generic_to_shared(Am);
    const uint32_t sBg = (uint32_t)__cvta_generic_to_shared(Bgs);
    const uint32_t sBu = (uint32_t)__cvta_generic_to_shared(Bus);
    const uint32_t aoff = (a_row * PA + a_seg) * 4;
    const uint32_t boff = (b_row * PB + b_col) * 4;
    const uint32_t szA = SZA_F * 4, szB = SZB_F * 4;

    float accg[2][4][4], accu[2][4][4];
#pragma unroll
    for (int i = 0; i < 2; i++)
#pragma unroll
        for (int j = 0; j < 4; j++)
#pragma unroll
            for (int c = 0; c < 4; c++) { accg[i][j][c] = 0.f; accu[i][j][c] = 0.f; }

#pragma unroll
    for (int l = 0; l < 4; l++) cp16(sAm + aoff + l * 16, a_src + l * 4);
    cp16(sBg + boff, bg_src);  cp16(sBg + boff + 16, bg_src + 4);
    cp16(sBu + boff, bu_src);  cp16(sBu + boff + 16, bu_src + 4);
    CP_COMMIT();

#pragma unroll 1
    for (int k0 = 0; k0 < DIM; k0 += BK) {
        const int cur = (k0 >> 5) & 1;
        if (k0 + BK < DIM) {
            const uint32_t nb = cur ^ 1;
#pragma unroll
            for (int l = 0; l < 4; l++)
                cp16(sAm + nb * szA + aoff + l * 16, a_src + k0 + BK + l * 4);
            const float* bgn = bg_src + (size_t)(k0 + BK) * FSH;
            const float* bun = bu_src + (size_t)(k0 + BK) * FSH;
            cp16(sBg + nb * szB + boff, bgn);  cp16(sBg + nb * szB + boff + 16, bgn + 4);
            cp16(sBu + nb * szB + boff, bun);  cp16(sBu + nb * szB + boff + 16, bun + 4);
        }
        CP_COMMIT();
        CP_WAIT1();
        __syncthreads();

        const float* A_  = Am  + cur * SZA_F;
        const float* BG_ = Bgs + cur * SZB_F;
        const float* BU_ = Bus + cur * SZB_F;
#pragma unroll
        for (int ks = 0; ks < 4; ks++) {
            const int kb = ks * 8;
            uint32_t af[2][4];
#pragma unroll
            for (int mt = 0; mt < 2; mt++) {
                int mr = wm + mt * 16 + q;
                af[mt][0] = f2tf32(A_[mr * PA + kb + r]);
                af[mt][1] = f2tf32(A_[(mr + 8) * PA + kb + r]);
                af[mt][2] = f2tf32(A_[mr * PA + kb + 4 + r]);
                af[mt][3] = f2tf32(A_[(mr + 8) * PA + kb + 4 + r]);
            }
            uint32_t bgf[4][2], buf[4][2];
#pragma unroll
            for (int nt = 0; nt < 4; nt++) {
                int nc = wn + nt * 8 + q;
                bgf[nt][0] = f2tf32(BG_[(kb + r) * PB + nc]);
                bgf[nt][1] = f2tf32(BG_[(kb + 4 + r) * PB + nc]);
                buf[nt][0] = f2tf32(BU_[(kb + r) * PB + nc]);
                buf[nt][1] = f2tf32(BU_[(kb + 4 + r) * PB + nc]);
            }
#pragma unroll
            for (int mt = 0; mt < 2; mt++)
#pragma unroll
                for (int nt = 0; nt < 4; nt++) {
                    mma_tf32(accg[mt][nt][0], accg[mt][nt][1], accg[mt][nt][2], accg[mt][nt][3],
                             af[mt][0], af[mt][1], af[mt][2], af[mt][3], bgf[nt][0], bgf[nt][1]);
                    mma_tf32(accu[mt][nt][0], accu[mt][nt][1], accu[mt][nt][2], accu[mt][nt][3],
                             af[mt][0], af[mt][1], af[mt][2], af[mt][3], buf[nt][0], buf[nt][1]);
                }
        }
        __syncthreads();
    }

#pragma unroll
    for (int mt = 0; mt < 2; mt++) {
        int r0 = wm + mt * 16 + q;
#pragma unroll
        for (int half = 0; half < 2; half++) {
            int m = rowbase + r0 + half * 8;
            float* dst = g_hs + (size_t)m * FSH + n0;
#pragma unroll
            for (int nt = 0; nt < 4; nt++) {
                int cb = wn + nt * 8 + 2 * r;
                float gv0 = accg[mt][nt][half * 2 + 0];
                float gv1 = accg[mt][nt][half * 2 + 1];
                float uv0 = accu[mt][nt][half * 2 + 0];
                float uv1 = accu[mt][nt][half * 2 + 1];
                dst[cb]     = (gv0 / (1.f + expf(-gv0))) * uv0;
                dst[cb + 1] = (gv1 / (1.f + expf(-gv1))) * uv1;
            }
        }
    }
}

// ---------------------------------------------------------------------------
// Shared down GEMM + final combine (BK=32)  grid: (NTOK/BM, DIM/BN)
// ---------------------------------------------------------------------------
__global__ __launch_bounds__(256)
void gemm_down_shared(const float* __restrict__ sh_down,
                      float* __restrict__ out)
{
    const int rowbase = blockIdx.x * BM;
    const int n0 = blockIdx.y * BN;

    extern __shared__ float smf[];
    float* Am = smf;
    float* Bs = smf + 2 * SZA_F;

    const int t = threadIdx.x;
    const int wid = t >> 5, lane = t & 31;
    const int q = lane >> 2, r = lane & 3;
    const int wm = (wid >> 1) * 32;
    const int wn = (wid & 1) * 32;

    const int a_row = t >> 1, a_seg = (t & 1) * 16;
    const float* a_src = g_hs + (size_t)(rowbase + a_row) * FSH + a_seg;

    const int b_row = t >> 3, b_col = (t & 7) * 8;
    const float* b_src = sh_down + (size_t)b_row * DIM + n0 + b_col;

    const uint32_t sAm = (uint32_t)__cvta_generic_to_shared(Am);
    const uint32_t sBs = (uint32_t)__cvta_generic_to_shared(Bs);
    const uint32_t aoff = (a_row * PA + a_seg) * 4;
    const uint32_t boff = (b_row * PB + b_col) * 4;
    const uint32_t szA = SZA_F * 4, szB = SZB_F * 4;

    float acc[2][4][4];
#pragma unroll
    for (int i = 0; i < 2; i++)
#pragma unroll
        for (int j = 0; j < 4; j++)
#pragma unroll
            for (int c = 0; c < 4; c++) acc[i][j][c] = 0.f;

#pragma unroll
    for (int l = 0; l < 4; l++) cp16(sAm + aoff + l * 16, a_src + l * 4);
    cp16(sBs + boff, b_src);  cp16(sBs + boff + 16, b_src + 4);
    CP_COMMIT();

#pragma unroll 1
    for (int k0 = 0; k0 < FSH; k0 += BK) {
        const int cur = (k0 >> 5) & 1;
        if (k0 + BK < FSH) {
            const uint32_t nb = cur ^ 1;
#pragma unroll
            for (int l = 0; l < 4; l++)
                cp16(sAm + nb * szA + aoff + l * 16, a_src + k0 + BK + l * 4);
            const float* bn = b_src + (size_t)(k0 + BK) * DIM;
            cp16(sBs + nb * szB + boff, bn);  cp16(sBs + nb * szB + boff + 16, bn + 4);
        }
        CP_COMMIT();
        CP_WAIT1();
        __syncthreads();

        const float* A_ = Am + cur * SZA_F;
        const float* B_ = Bs + cur * SZB_F;
#pragma unroll
        for (int ks = 0; ks < 4; ks++) {
            const int kb = ks * 8;
            uint32_t af[2][4];
#pragma unroll
            for (int mt = 0; mt < 2; mt++) {
                int mr = wm + mt * 16 + q;
                af[mt][0] = f2tf32(A_[mr * PA + kb + r]);
                af[mt][1] = f2tf32(A_[(mr + 8) * PA + kb + r]);
                af[mt][2] = f2tf32(A_[mr * PA + kb + 4 + r]);
                af[mt][3] = f2tf32(A_[(mr + 8) * PA + kb + 4 + r]);
            }
            uint32_t bf[4][2];
#pragma unroll
            for (int nt = 0; nt < 4; nt++) {
                int nc = wn + nt * 8 + q;
                bf[nt][0] = f2tf32(B_[(kb + r) * PB + nc]);
                bf[nt][1] = f2tf32(B_[(kb + 4 + r) * PB + nc]);
            }
#pragma unroll
            for (int mt = 0; mt < 2; mt++)
#pragma unroll
                for (int nt = 0; nt < 4; nt++)
                    mma_tf32(acc[mt][nt][0], acc[mt][nt][1], acc[mt][nt][2], acc[mt][nt][3],
                             af[mt][0], af[mt][1], af[mt][2], af[mt][3], bf[nt][0], bf[nt][1]);
        }
        __syncthreads();
    }

#pragma unroll
    for (int mt = 0; mt < 2; mt++) {
        int r0 = wm + mt * 16 + q;
#pragma unroll
        for (int half = 0; half < 2; half++) {
            int m = rowbase + r0 + half * 8;
            const float* eo0 = g_eo + (size_t)(m * 2)     * DIM + n0;
            const float* eo1 = g_eo + (size_t)(m * 2 + 1) * DIM + n0;
            float* dst = out + (size_t)m * DIM + n0;
#pragma unroll
            for (int nt = 0; nt < 4; nt++) {
                int cb = wn + nt * 8 + 2 * r;
                dst[cb]     = acc[mt][nt][half * 2 + 0] + eo0[cb]     + eo1[cb];
                dst[cb + 1] = acc[mt][nt][half * 2 + 1] + eo0[cb + 1] + eo1[cb + 1];
            }
        }
    }
}

// ---------------------------------------------------------------------------
extern "C" void kernel_launch(void* const* d_in, const int* in_sizes, int n_in,
                              void* d_out, int out_size)
{
    const float* x       = (const float*)d_in[0];
    const float* gate_w  = (const float*)d_in[1];
    const float* gate_k  = (const float*)d_in[2];
    const float* up_k    = (const float*)d_in[3];
    const float* down_k  = (const float*)d_in[4];
    const float* sh_gate = (const float*)d_in[5];
    const float* sh_up   = (const float*)d_in[6];
    const float* sh_down = (const float*)d_in[7];
    float* out = (float*)d_out;

    cudaFuncSetAttribute(gemm_gateup_routed,
                         cudaFuncAttributeMaxDynamicSharedMemorySize, SMEM_DUAL_B);
    cudaFuncSetAttribute(gemm_gateup_shared,
                         cudaFuncAttributeMaxDynamicSharedMemorySize, SMEM_DUAL_B);
    cudaFuncSetAttribute(gemm_down_routed,
                         cudaFuncAttributeMaxDynamicSharedMemorySize, SMEM_SING_B);
    cudaFuncSetAttribute(gemm_down_shared,
                         cudaFuncAttributeMaxDynamicSharedMemorySize, SMEM_SING_B);

    zero_cnt_kernel<<<1, 32>>>();
    router_kernel<<<NTOK, 128>>>(x, gate_w);
    scan_kernel<<<1, 32>>>();
    fill_kernel<<<NTOK / 256, 256>>>();

    gemm_gateup_routed<<<dim3(NTOK / BM, FF / BN, NE), 256, SMEM_DUAL_B>>>(x, gate_k, up_k);
    gemm_down_routed<<<dim3(NTOK / BM, DIM / BN, NE), 256, SMEM_SING_B>>>(down_k);
    gemm_gateup_shared<<<dim3(NTOK / BM, FSH / BN), 256, SMEM_DUAL_B>>>(x, sh_gate, sh_up);
    gemm_down_shared<<<dim3(NTOK / BM, DIM / BN), 256, SMEM_SING_B>>>(sh_down, out);
}

// round 9
// speedup vs baseline: 1.0820x; 1.0647x over previous
#include <cuda_runtime.h>
#include <math.h>
#include <stdint.h>

// Problem constants
#define NTOK 2048
#define DIM  1024
#define FF   4096
#define FSH  2048
#define NE   8
#define TOPK 2
#define NSLOT (NTOK*TOPK)

// Tiling: BM=128, BN=64, BK=16, 3-stage cp.async pipeline, dynamic smem
#define BM 128
#define BN 64
#define BK 16
#define PA 20      // A smem pitch [m][k]
#define PB 72      // B smem pitch [k][n]

#define SZA_F (BM * PA)                    // 2560 floats
#define SZB_F (BK * PB)                    // 1152 floats
#define SMEM_DUAL ((3*SZA_F + 6*SZB_F) * 4)   // 58368 B
#define SMEM_SING ((3*SZA_F + 3*SZB_F) * 4)   // 44544 B

// ---- scratch ----
__device__ float g_act[(size_t)NSLOT * FF];
__device__ float g_eo[(size_t)NSLOT * DIM];
__device__ float g_hs[(size_t)NTOK * FSH];
__device__ float g_topw[NTOK * TOPK];
__device__ int   g_topi[NTOK * TOPK];
__device__ int   g_slot_tok[NSLOT];
__device__ float g_slot_w[NSLOT];
__device__ int   g_slot_dst[NSLOT];
__device__ int   g_cnt[NE];
__device__ int   g_off[NE + 1];

// ---------------------------------------------------------------------------
__device__ __forceinline__ uint32_t f2tf32(float x) {
    uint32_t r;
    asm("cvt.rna.tf32.f32 %0, %1;" : "=r"(r) : "f"(x));
    return r;
}

__device__ __forceinline__ void mma_tf32(float& c0, float& c1, float& c2, float& c3,
                                         uint32_t a0, uint32_t a1, uint32_t a2, uint32_t a3,
                                         uint32_t b0, uint32_t b1)
{
    asm volatile(
        "mma.sync.aligned.m16n8k8.row.col.f32.tf32.tf32.f32 "
        "{%0,%1,%2,%3},{%4,%5,%6,%7},{%8,%9},{%0,%1,%2,%3};"
        : "+f"(c0), "+f"(c1), "+f"(c2), "+f"(c3)
        : "r"(a0), "r"(a1), "r"(a2), "r"(a3), "r"(b0), "r"(b1));
}

__device__ __forceinline__ void cp16(uint32_t dst_smem, const float* src) {
    asm volatile("cp.async.cg.shared.global [%0], [%1], 16;"
                 :: "r"(dst_smem), "l"(src));
}
#define CP_COMMIT() asm volatile("cp.async.commit_group;")
#define CP_WAIT1()  asm volatile("cp.async.wait_group 1;" ::: "memory")

// ---------------------------------------------------------------------------
// Router + compaction (validated, unchanged)
// ---------------------------------------------------------------------------
__global__ void router_kernel(const float* __restrict__ x,
                              const float* __restrict__ gate_w)
{
    const int n = blockIdx.x;
    const int tid = threadIdx.x;
    __shared__ float sred[NE][128];

    float acc[NE];
#pragma unroll
    for (int e = 0; e < NE; e++) acc[e] = 0.f;

    const float* xr = x + (size_t)n * DIM;
    for (int d = tid; d < DIM; d += 128) {
        float xv = xr[d];
#pragma unroll
        for (int e = 0; e < NE; e++)
            acc[e] = fmaf(xv, gate_w[e * DIM + d], acc[e]);
    }
#pragma unroll
    for (int e = 0; e < NE; e++) sred[e][tid] = acc[e];
    __syncthreads();

    if (tid < NE) {
        float s = 0.f;
        for (int i = 0; i < 128; i++) s += sred[tid][i];
        sred[tid][0] = s;
    }
    __syncthreads();

    if (tid == 0) {
        float lg[NE];
#pragma unroll
        for (int e = 0; e < NE; e++) lg[e] = sred[e][0];
        float mx = lg[0];
#pragma unroll
        for (int e = 1; e < NE; e++) mx = fmaxf(mx, lg[e]);
        float se = 0.f, p[NE];
#pragma unroll
        for (int e = 0; e < NE; e++) { p[e] = expf(lg[e] - mx); se += p[e]; }
        float inv = 1.f / se;
#pragma unroll
        for (int e = 0; e < NE; e++) p[e] *= inv;

        int i1 = 0; float v1 = p[0];
#pragma unroll
        for (int e = 1; e < NE; e++) if (p[e] > v1) { v1 = p[e]; i1 = e; }
        int i2 = -1; float v2 = -1.f;
#pragma unroll
        for (int e = 0; e < NE; e++) if (e != i1 && p[e] > v2) { v2 = p[e]; i2 = e; }

        g_topi[n * 2 + 0] = i1;  g_topw[n * 2 + 0] = v1;
        g_topi[n * 2 + 1] = i2;  g_topw[n * 2 + 1] = v2;
        atomicAdd(&g_cnt[i1], 1);
        atomicAdd(&g_cnt[i2], 1);
    }
}

__global__ void zero_cnt_kernel()
{
    if (threadIdx.x < NE) g_cnt[threadIdx.x] = 0;
}

__global__ void scan_kernel()
{
    if (threadIdx.x == 0) {
        int r = 0;
        for (int e = 0; e < NE; e++) { g_off[e] = r; r += g_cnt[e]; g_cnt[e] = 0; }
        g_off[NE] = r;
    }
}

__global__ void fill_kernel()
{
    int n = blockIdx.x * blockDim.x + threadIdx.x;
    if (n >= NTOK) return;
#pragma unroll
    for (int k = 0; k < TOPK; k++) {
        int e = g_topi[n * 2 + k];
        int pos = atomicAdd(&g_cnt[e], 1);
        int slot = g_off[e] + pos;
        g_slot_tok[slot] = n;
        g_slot_w[slot]   = g_topw[n * 2 + k];
        g_slot_dst[slot] = n * 2 + k;
    }
}

// ---------------------------------------------------------------------------
// Routed gate+up GEMM + SwiGLU + weight (3-stage pipeline, 1 barrier/chunk)
// grid: (FF/BN, NTOK/BM, NE)
// ---------------------------------------------------------------------------
__global__ __launch_bounds__(256, 2)
void gemm_gateup_routed(const float* __restrict__ x,
                        const float* __restrict__ gate_k,
                        const float* __restrict__ up_k)
{
    const int e = blockIdx.z;
    const int cnt = g_cnt[e];
    const int rowbase = blockIdx.y * BM;
    if (rowbase >= cnt) return;
    const int off = g_off[e];
    const int n0 = blockIdx.x * BN;
    const float* __restrict__ Bg = gate_k + (size_t)e * DIM * FF;
    const float* __restrict__ Bu = up_k   + (size_t)e * DIM * FF;

    extern __shared__ float smf[];
    float* Am  = smf;                          // 3 x SZA_F
    float* Bgs = smf + 3 * SZA_F;              // 3 x SZB_F
    float* Bus = smf + 3 * SZA_F + 3 * SZB_F;  // 3 x SZB_F

    const int t = threadIdx.x;
    const int wid = t >> 5, lane = t & 31;
    const int q = lane >> 2, r = lane & 3;
    const int wm = (wid >> 1) * 32;
    const int wn = (wid & 1) * 32;

    const int a_row = t >> 1, a_seg = (t & 1) * 8;
    int m_g = rowbase + a_row;
    if (m_g >= cnt) m_g = cnt - 1;
    const float* a_src = x + (size_t)g_slot_tok[off + m_g] * DIM + a_seg;

    const int b_row = t >> 4, b_col = (t & 15) * 4;
    const float* bg_src = Bg + (size_t)b_row * FF + n0 + b_col;
    const float* bu_src = Bu + (size_t)b_row * FF + n0 + b_col;

    const uint32_t sAm = (uint32_t)__cvta_generic_to_shared(Am);
    const uint32_t sBg = (uint32_t)__cvta_generic_to_shared(Bgs);
    const uint32_t sBu = (uint32_t)__cvta_generic_to_shared(Bus);
    const uint32_t aoff = (a_row * PA + a_seg) * 4;
    const uint32_t boff = (b_row * PB + b_col) * 4;
    const uint32_t szA = SZA_F * 4, szB = SZB_F * 4;

    float accg[2][4][4], accu[2][4][4];
#pragma unroll
    for (int i = 0; i < 2; i++)
#pragma unroll
        for (int j = 0; j < 4; j++)
#pragma unroll
            for (int c = 0; c < 4; c++) { accg[i][j][c] = 0.f; accu[i][j][c] = 0.f; }

    // prologue: chunks 0,1 into buffers 0,1
#pragma unroll
    for (int p = 0; p < 2; p++) {
        cp16(sAm + p * szA + aoff,      a_src + p * BK);
        cp16(sAm + p * szA + aoff + 16, a_src + p * BK + 4);
        cp16(sBg + p * szB + boff, bg_src + (size_t)(p * BK) * FF);
        cp16(sBu + p * szB + boff, bu_src + (size_t)(p * BK) * FF);
        CP_COMMIT();
    }

    const int NC = DIM / BK;
    int bi = 0;                 // buffer of current chunk
    int wi = 2;                 // buffer for prefetch (c+2)
#pragma unroll 1
    for (int c = 0; c < NC; c++) {
        CP_WAIT1();
        __syncthreads();

        if (c + 2 < NC) {
            const int kk = (c + 2) * BK;
            cp16(sAm + wi * szA + aoff,      a_src + kk);
            cp16(sAm + wi * szA + aoff + 16, a_src + kk + 4);
            cp16(sBg + wi * szB + boff, bg_src + (size_t)kk * FF);
            cp16(sBu + wi * szB + boff, bu_src + (size_t)kk * FF);
        }
        CP_COMMIT();

        const float* A_  = Am  + bi * SZA_F;
        const float* BG_ = Bgs + bi * SZB_F;
        const float* BU_ = Bus + bi * SZB_F;
#pragma unroll
        for (int ks = 0; ks < 2; ks++) {
            const int kb = ks * 8;
            uint32_t af[2][4];
#pragma unroll
            for (int mt = 0; mt < 2; mt++) {
                int mr = wm + mt * 16 + q;
                af[mt][0] = f2tf32(A_[mr * PA + kb + r]);
                af[mt][1] = f2tf32(A_[(mr + 8) * PA + kb + r]);
                af[mt][2] = f2tf32(A_[mr * PA + kb + 4 + r]);
                af[mt][3] = f2tf32(A_[(mr + 8) * PA + kb + 4 + r]);
            }
            uint32_t bgf[4][2], buf[4][2];
#pragma unroll
            for (int nt = 0; nt < 4; nt++) {
                int nc = wn + nt * 8 + q;
                bgf[nt][0] = f2tf32(BG_[(kb + r) * PB + nc]);
                bgf[nt][1] = f2tf32(BG_[(kb + 4 + r) * PB + nc]);
                buf[nt][0] = f2tf32(BU_[(kb + r) * PB + nc]);
                buf[nt][1] = f2tf32(BU_[(kb + 4 + r) * PB + nc]);
            }
#pragma unroll
            for (int mt = 0; mt < 2; mt++)
#pragma unroll
                for (int nt = 0; nt < 4; nt++) {
                    mma_tf32(accg[mt][nt][0], accg[mt][nt][1], accg[mt][nt][2], accg[mt][nt][3],
                             af[mt][0], af[mt][1], af[mt][2], af[mt][3], bgf[nt][0], bgf[nt][1]);
                    mma_tf32(accu[mt][nt][0], accu[mt][nt][1], accu[mt][nt][2], accu[mt][nt][3],
                             af[mt][0], af[mt][1], af[mt][2], af[mt][3], buf[nt][0], buf[nt][1]);
                }
        }
        bi = (bi == 2) ? 0 : bi + 1;
        wi = (wi == 2) ? 0 : wi + 1;
    }

#pragma unroll
    for (int mt = 0; mt < 2; mt++) {
        int r0 = wm + mt * 16 + q;
#pragma unroll
        for (int half = 0; half < 2; half++) {
            int m = rowbase + r0 + half * 8;
            if (m < cnt) {
                int slot = off + m;
                float w = g_slot_w[slot];
                float* dst = g_act + (size_t)slot * FF + n0;
#pragma unroll
                for (int nt = 0; nt < 4; nt++) {
                    int cb = wn + nt * 8 + 2 * r;
                    float gv0 = accg[mt][nt][half * 2 + 0];
                    float gv1 = accg[mt][nt][half * 2 + 1];
                    float uv0 = accu[mt][nt][half * 2 + 0];
                    float uv1 = accu[mt][nt][half * 2 + 1];
                    dst[cb]     = w * (gv0 / (1.f + expf(-gv0))) * uv0;
                    dst[cb + 1] = w * (gv1 / (1.f + expf(-gv1))) * uv1;
                }
            }
        }
    }
}

// ---------------------------------------------------------------------------
// Routed down GEMM (3-stage pipeline)  grid: (DIM/BN, NTOK/BM, NE)
// ---------------------------------------------------------------------------
__global__ __launch_bounds__(256, 2)
void gemm_down_routed(const float* __restrict__ down_k)
{
    const int e = blockIdx.z;
    const int cnt = g_cnt[e];
    const int rowbase = blockIdx.y * BM;
    if (rowbase >= cnt) return;
    const int off = g_off[e];
    const int n0 = blockIdx.x * BN;
    const float* __restrict__ B = down_k + (size_t)e * FF * DIM;

    extern __shared__ float smf[];
    float* Am = smf;
    float* Bs = smf + 3 * SZA_F;

    const int t = threadIdx.x;
    const int wid = t >> 5, lane = t & 31;
    const int q = lane >> 2, r = lane & 3;
    const int wm = (wid >> 1) * 32;
    const int wn = (wid & 1) * 32;

    const int a_row = t >> 1, a_seg = (t & 1) * 8;
    int m_g = rowbase + a_row;
    if (m_g >= cnt) m_g = cnt - 1;
    const float* a_src = g_act + (size_t)(off + m_g) * FF + a_seg;

    const int b_row = t >> 4, b_col = (t & 15) * 4;
    const float* b_src = B + (size_t)b_row * DIM + n0 + b_col;

    const uint32_t sAm = (uint32_t)__cvta_generic_to_shared(Am);
    const uint32_t sBs = (uint32_t)__cvta_generic_to_shared(Bs);
    const uint32_t aoff = (a_row * PA + a_seg) * 4;
    const uint32_t boff = (b_row * PB + b_col) * 4;
    const uint32_t szA = SZA_F * 4, szB = SZB_F * 4;

    float acc[2][4][4];
#pragma unroll
    for (int i = 0; i < 2; i++)
#pragma unroll
        for (int j = 0; j < 4; j++)
#pragma unroll
            for (int c = 0; c < 4; c++) acc[i][j][c] = 0.f;

#pragma unroll
    for (int p = 0; p < 2; p++) {
        cp16(sAm + p * szA + aoff,      a_src + p * BK);
        cp16(sAm + p * szA + aoff + 16, a_src + p * BK + 4);
        cp16(sBs + p * szB + boff, b_src + (size_t)(p * BK) * DIM);
        CP_COMMIT();
    }

    const int NC = FF / BK;
    int bi = 0, wi = 2;
#pragma unroll 1
    for (int c = 0; c < NC; c++) {
        CP_WAIT1();
        __syncthreads();

        if (c + 2 < NC) {
            const int kk = (c + 2) * BK;
            cp16(sAm + wi * szA + aoff,      a_src + kk);
            cp16(sAm + wi * szA + aoff + 16, a_src + kk + 4);
            cp16(sBs + wi * szB + boff, b_src + (size_t)kk * DIM);
        }
        CP_COMMIT();

        const float* A_ = Am + bi * SZA_F;
        const float* B_ = Bs + bi * SZB_F;
#pragma unroll
        for (int ks = 0; ks < 2; ks++) {
            const int kb = ks * 8;
            uint32_t af[2][4];
#pragma unroll
            for (int mt = 0; mt < 2; mt++) {
                int mr = wm + mt * 16 + q;
                af[mt][0] = f2tf32(A_[mr * PA + kb + r]);
                af[mt][1] = f2tf32(A_[(mr + 8) * PA + kb + r]);
                af[mt][2] = f2tf32(A_[mr * PA + kb + 4 + r]);
                af[mt][3] = f2tf32(A_[(mr + 8) * PA + kb + 4 + r]);
            }
            uint32_t bf[4][2];
#pragma unroll
            for (int nt = 0; nt < 4; nt++) {
                int nc = wn + nt * 8 + q;
                bf[nt][0] = f2tf32(B_[(kb + r) * PB + nc]);
                bf[nt][1] = f2tf32(B_[(kb + 4 + r) * PB + nc]);
            }
#pragma unroll
            for (int mt = 0; mt < 2; mt++)
#pragma unroll
                for (int nt = 0; nt < 4; nt++)
                    mma_tf32(acc[mt][nt][0], acc[mt][nt][1], acc[mt][nt][2], acc[mt][nt][3],
                             af[mt][0], af[mt][1], af[mt][2], af[mt][3], bf[nt][0], bf[nt][1]);
        }
        bi = (bi == 2) ? 0 : bi + 1;
        wi = (wi == 2) ? 0 : wi + 1;
    }

#pragma unroll
    for (int mt = 0; mt < 2; mt++) {
        int r0 = wm + mt * 16 + q;
#pragma unroll
        for (int half = 0; half < 2; half++) {
            int m = rowbase + r0 + half * 8;
            if (m < cnt) {
                int dst_row = g_slot_dst[off + m];
                float* dst = g_eo + (size_t)dst_row * DIM + n0;
#pragma unroll
                for (int nt = 0; nt < 4; nt++) {
                    int cb = wn + nt * 8 + 2 * r;
                    dst[cb]     = acc[mt][nt][half * 2 + 0];
                    dst[cb + 1] = acc[mt][nt][half * 2 + 1];
                }
            }
        }
    }
}

// ---------------------------------------------------------------------------
// Shared expert gate+up + SwiGLU (3-stage pipeline)  grid: (FSH/BN, NTOK/BM)
// ---------------------------------------------------------------------------
__global__ __launch_bounds__(256, 2)
void gemm_gateup_shared(const float* __restrict__ x,
                        const float* __restrict__ sh_gate,
                        const float* __restrict__ sh_up)
{
    const int rowbase = blockIdx.y * BM;
    const int n0 = blockIdx.x * BN;

    extern __shared__ float smf[];
    float* Am  = smf;
    float* Bgs = smf + 3 * SZA_F;
    float* Bus = smf + 3 * SZA_F + 3 * SZB_F;

    const int t = threadIdx.x;
    const int wid = t >> 5, lane = t & 31;
    const int q = lane >> 2, r = lane & 3;
    const int wm = (wid >> 1) * 32;
    const int wn = (wid & 1) * 32;

    const int a_row = t >> 1, a_seg = (t & 1) * 8;
    const float* a_src = x + (size_t)(rowbase + a_row) * DIM + a_seg;

    const int b_row = t >> 4, b_col = (t & 15) * 4;
    const float* bg_src = sh_gate + (size_t)b_row * FSH + n0 + b_col;
    const float* bu_src = sh_up   + (size_t)b_row * FSH + n0 + b_col;

    const uint32_t sAm = (uint32_t)__cvta_generic_to_shared(Am);
    const uint32_t sBg = (uint32_t)__cvta_generic_to_shared(Bgs);
    const uint32_t sBu = (uint32_t)__cvta_generic_to_shared(Bus);
    const uint32_t aoff = (a_row * PA + a_seg) * 4;
    const uint32_t boff = (b_row * PB + b_col) * 4;
    const uint32_t szA = SZA_F * 4, szB = SZB_F * 4;

    float accg[2][4][4], accu[2][4][4];
#pragma unroll
    for (int i = 0; i < 2; i++)
#pragma unroll
        for (int j = 0; j < 4; j++)
#pragma unroll
            for (int c = 0; c < 4; c++) { accg[i][j][c] = 0.f; accu[i][j][c] = 0.f; }

#pragma unroll
    for (int p = 0; p < 2; p++) {
        cp16(sAm + p * szA + aoff,      a_src + p * BK);
        cp16(sAm + p * szA + aoff + 16, a_src + p * BK + 4);
        cp16(sBg + p * szB + boff, bg_src + (size_t)(p * BK) * FSH);
        cp16(sBu + p * szB + boff, bu_src + (size_t)(p * BK) * FSH);
        CP_COMMIT();
    }

    const int NC = DIM / BK;
    int bi = 0, wi = 2;
#pragma unroll 1
    for (int c = 0; c < NC; c++) {
        CP_WAIT1();
        __syncthreads();

        if (c + 2 < NC) {
            const int kk = (c + 2) * BK;
            cp16(sAm + wi * szA + aoff,      a_src + kk);
            cp16(sAm + wi * szA + aoff + 16, a_src + kk + 4);
            cp16(sBg + wi * szB + boff, bg_src + (size_t)kk * FSH);
            cp16(sBu + wi * szB + boff, bu_src + (size_t)kk * FSH);
        }
        CP_COMMIT();

        const float* A_  = Am  + bi * SZA_F;
        const float* BG_ = Bgs + bi * SZB_F;
        const float* BU_ = Bus + bi * SZB_F;
#pragma unroll
        for (int ks = 0; ks < 2; ks++) {
            const int kb = ks * 8;
            uint32_t af[2][4];
#pragma unroll
            for (int mt = 0; mt < 2; mt++) {
                int mr = wm + mt * 16 + q;
                af[mt][0] = f2tf32(A_[mr * PA + kb + r]);
                af[mt][1] = f2tf32(A_[(mr + 8) * PA + kb + r]);
                af[mt][2] = f2tf32(A_[mr * PA + kb + 4 + r]);
                af[mt][3] = f2tf32(A_[(mr + 8) * PA + kb + 4 + r]);
            }
            uint32_t bgf[4][2], buf[4][2];
#pragma unroll
            for (int nt = 0; nt < 4; nt++) {
                int nc = wn + nt * 8 + q;
                bgf[nt][0] = f2tf32(BG_[(kb + r) * PB + nc]);
                bgf[nt][1] = f2tf32(BG_[(kb + 4 + r) * PB + nc]);
                buf[nt][0] = f2tf32(BU_[(kb + r) * PB + nc]);
                buf[nt][1] = f2tf32(BU_[(kb + 4 + r) * PB + nc]);
            }
#pragma unroll
            for (int mt = 0; mt < 2; mt++)
#pragma unroll
                for (int nt = 0; nt < 4; nt++) {
                    mma_tf32(accg[mt][nt][0], accg[mt][nt][1], accg[mt][nt][2], accg[mt][nt][3],
                             af[mt][0], af[mt][1], af[mt][2], af[mt][3], bgf[nt][0], bgf[nt][1]);
                    mma_tf32(accu[mt][nt][0], accu[mt][nt][1], accu[mt][nt][2], accu[mt][nt][3],
                             af[mt][0], af[mt][1], af[mt][2], af[mt][3], buf[nt][0], buf[nt][1]);
                }
        }
        bi = (bi == 2) ? 0 : bi + 1;
        wi = (wi == 2) ? 0 : wi + 1;
    }

#pragma unroll
    for (int mt = 0; mt < 2; mt++) {
        int r0 = wm + mt * 16 + q;
#pragma unroll
        for (int half = 0; half < 2; half++) {
            int m = rowbase + r0 + half * 8;
            float* dst = g_hs + (size_t)m * FSH + n0;
#pragma unroll
            for (int nt = 0; nt < 4; nt++) {
                int cb = wn + nt * 8 + 2 * r;
                float gv0 = accg[mt][nt][half * 2 + 0];
                float gv1 = accg[mt][nt][half * 2 + 1];
                float uv0 = accu[mt][nt][half * 2 + 0];
                float uv1 = accu[mt][nt][half * 2 + 1];
                dst[cb]     = (gv0 / (1.f + expf(-gv0))) * uv0;
                dst[cb + 1] = (gv1 / (1.f + expf(-gv1))) * uv1;
            }
        }
    }
}

// ---------------------------------------------------------------------------
// Shared down GEMM + final combine (3-stage pipeline)  grid: (DIM/BN, NTOK/BM)
// ---------------------------------------------------------------------------
__global__ __launch_bounds__(256, 2)
void gemm_down_shared(const float* __restrict__ sh_down,
                      float* __restrict__ out)
{
    const int rowbase = blockIdx.y * BM;
    const int n0 = blockIdx.x * BN;

    extern __shared__ float smf[];
    float* Am = smf;
    float* Bs = smf + 3 * SZA_F;

    const int t = threadIdx.x;
    const int wid = t >> 5, lane = t & 31;
    const int q = lane >> 2, r = lane & 3;
    const int wm = (wid >> 1) * 32;
    const int wn = (wid & 1) * 32;

    const int a_row = t >> 1, a_seg = (t & 1) * 8;
    const float* a_src = g_hs + (size_t)(rowbase + a_row) * FSH + a_seg;

    const int b_row = t >> 4, b_col = (t & 15) * 4;
    const float* b_src = sh_down + (size_t)b_row * DIM + n0 + b_col;

    const uint32_t sAm = (uint32_t)__cvta_generic_to_shared(Am);
    const uint32_t sBs = (uint32_t)__cvta_generic_to_shared(Bs);
    const uint32_t aoff = (a_row * PA + a_seg) * 4;
    const uint32_t boff = (b_row * PB + b_col) * 4;
    const uint32_t szA = SZA_F * 4, szB = SZB_F * 4;

    float acc[2][4][4];
#pragma unroll
    for (int i = 0; i < 2; i++)
#pragma unroll
        for (int j = 0; j < 4; j++)
#pragma unroll
            for (int c = 0; c < 4; c++) acc[i][j][c] = 0.f;

#pragma unroll
    for (int p = 0; p < 2; p++) {
        cp16(sAm + p * szA + aoff,      a_src + p * BK);
        cp16(sAm + p * szA + aoff + 16, a_src + p * BK + 4);
        cp16(sBs + p * szB + boff, b_src + (size_t)(p * BK) * DIM);
        CP_COMMIT();
    }

    const int NC = FSH / BK;
    int bi = 0, wi = 2;
#pragma unroll 1
    for (int c = 0; c < NC; c++) {
        CP_WAIT1();
        __syncthreads();

        if (c + 2 < NC) {
            const int kk = (c + 2) * BK;
            cp16(sAm + wi * szA + aoff,      a_src + kk);
            cp16(sAm + wi * szA + aoff + 16, a_src + kk + 4);
            cp16(sBs + wi * szB + boff, b_src + (size_t)kk * DIM);
        }
        CP_COMMIT();

        const float* A_ = Am + bi * SZA_F;
        const float* B_ = Bs + bi * SZB_F;
#pragma unroll
        for (int ks = 0; ks < 2; ks++) {
            const int kb = ks * 8;
            uint32_t af[2][4];
#pragma unroll
            for (int mt = 0; mt < 2; mt++) {
                int mr = wm + mt * 16 + q;
                af[mt][0] = f2tf32(A_[mr * PA + kb + r]);
                af[mt][1] = f2tf32(A_[(mr + 8) * PA + kb + r]);
                af[mt][2] = f2tf32(A_[mr * PA + kb + 4 + r]);
                af[mt][3] = f2tf32(A_[(mr + 8) * PA + kb + 4 + r]);
            }
            uint32_t bf[4][2];
#pragma unroll
            for (int nt = 0; nt < 4; nt++) {
                int nc = wn + nt * 8 + q;
                bf[nt][0] = f2tf32(B_[(kb + r) * PB + nc]);
                bf[nt][1] = f2tf32(B_[(kb + 4 + r) * PB + nc]);
            }
#pragma unroll
            for (int mt = 0; mt < 2; mt++)
#pragma unroll
                for (int nt = 0; nt < 4; nt++)
                    mma_tf32(acc[mt][nt][0], acc[mt][nt][1], acc[mt][nt][2], acc[mt][nt][3],
                             af[mt][0], af[mt][1], af[mt][2], af[mt][3], bf[nt][0], bf[nt][1]);
        }
        bi = (bi == 2) ? 0 : bi + 1;
        wi = (wi == 2) ? 0 : wi + 1;
    }

#pragma unroll
    for (int mt = 0; mt < 2; mt++) {
        int r0 = wm + mt * 16 + q;
#pragma unroll
        for (int half = 0; half < 2; half++) {
            int m = rowbase + r0 + half * 8;
            const float* eo0 = g_eo + (size_t)(m * 2)     * DIM + n0;
            const float* eo1 = g_eo + (size_t)(m * 2 + 1) * DIM + n0;
            float* dst = out + (size_t)m * DIM + n0;
#pragma unroll
            for (int nt = 0; nt < 4; nt++) {
                int cb = wn + nt * 8 + 2 * r;
                dst[cb]     = acc[mt][nt][half * 2 + 0] + eo0[cb]     + eo1[cb];
                dst[cb + 1] = acc[mt][nt][half * 2 + 1] + eo0[cb + 1] + eo1[cb + 1];
            }
        }
    }
}

// ---------------------------------------------------------------------------
extern "C" void kernel_launch(void* const* d_in, const int* in_sizes, int n_in,
                              void* d_out, int out_size)
{
    const float* x       = (const float*)d_in[0];
    const float* gate_w  = (const float*)d_in[1];
    const float* gate_k  = (const float*)d_in[2];
    const float* up_k    = (const float*)d_in[3];
    const float* down_k  = (const float*)d_in[4];
    const float* sh_gate = (const float*)d_in[5];
    const float* sh_up   = (const float*)d_in[6];
    const float* sh_down = (const float*)d_in[7];
    float* out = (float*)d_out;

    cudaFuncSetAttribute(gemm_gateup_routed,
                         cudaFuncAttributeMaxDynamicSharedMemorySize, SMEM_DUAL);
    cudaFuncSetAttribute(gemm_gateup_shared,
                         cudaFuncAttributeMaxDynamicSharedMemorySize, SMEM_DUAL);
    cudaFuncSetAttribute(gemm_down_routed,
                         cudaFuncAttributeMaxDynamicSharedMemorySize, SMEM_SING);
    cudaFuncSetAttribute(gemm_down_shared,
                         cudaFuncAttributeMaxDynamicSharedMemorySize, SMEM_SING);

    zero_cnt_kernel<<<1, 32>>>();
    router_kernel<<<NTOK, 128>>>(x, gate_w);
    scan_kernel<<<1, 32>>>();
    fill_kernel<<<NTOK / 256, 256>>>();

    gemm_gateup_routed<<<dim3(FF / BN, NTOK / BM, NE), 256, SMEM_DUAL>>>(x, gate_k, up_k);
    gemm_down_routed<<<dim3(DIM / BN, NTOK / BM, NE), 256, SMEM_SING>>>(down_k);
    gemm_gateup_shared<<<dim3(FSH / BN, NTOK / BM), 256, SMEM_DUAL>>>(x, sh_gate, sh_up);
    gemm_down_shared<<<dim3(DIM / BN, NTOK / BM), 256, SMEM_SING>>>(sh_down, out);
}